// round 2
// baseline (speedup 1.0000x reference)
#include <cuda_runtime.h>
#include <math.h>

#define BB 4
#define QQ 256
#define CCN 1024
#define QDIM 512
#define CDIM 512
#define HH 128

// ---------------- scratch (device globals; no allocation) ----------------
__device__ float g_mc[BB * CCN * HH];        // (B,C,H)   2MB
__device__ float g_mq[BB * QQ * HH];         // (B,Q,H)   512KB
__device__ float g_qpart[BB * QQ * QDIM];    // (B,Q,QD)  2MB : query @ lo_w[:,512:].T + lo_b
__device__ float g_wc[BB * QQ * CDIM];       // (B,Q,CD)  2MB : attn @ context
__device__ float g_attn_scratch[BB * QQ * CCN]; // fallback if attn not in d_out

// ---------------- generic tiled SGEMM: C = act(A @ op(B) + bias + Add) ----
// A: [M,K] row-major (lda). TRANSB: B is [N,K] (ldb) ; else B is [K,N] (ldb).
// Tile 64x64x16, 256 threads, 4x4 per-thread tile. M,N mult of 64, K mult of 16.
template <bool TRANSB, bool HAS_BIAS, bool HAS_ADD, bool DO_TANH>
__global__ __launch_bounds__(256)
void sgemm64(const float* __restrict__ A, int lda, long sA,
             const float* __restrict__ Bm, int ldb, long sB,
             const float* __restrict__ bias,
             const float* __restrict__ Add,
             float* __restrict__ C, int ldc, long sC,
             int K)
{
    __shared__ float As[16][64];
    __shared__ float Bs[16][64];

    const int bz = blockIdx.z;
    A  += (long)bz * sA;
    Bm += (long)bz * sB;
    C  += (long)bz * sC;
    const float* AddB = HAS_ADD ? (Add + (long)bz * sC) : nullptr;

    const int m0 = blockIdx.y * 64;
    const int n0 = blockIdx.x * 64;
    const int tid = threadIdx.x;
    const int tx = tid & 15;       // 0..15 (n)
    const int ty = tid >> 4;       // 0..15 (m)

    // loader indices (64 rows x 16 cols, one float4 per thread)
    const int ar  = tid >> 2;            // 0..63
    const int ac4 = (tid & 3) * 4;       // 0,4,8,12

    float acc[4][4];
#pragma unroll
    for (int i = 0; i < 4; i++)
#pragma unroll
        for (int j = 0; j < 4; j++) acc[i][j] = 0.f;

    for (int k0 = 0; k0 < K; k0 += 16) {
        // load A tile (transpose into smem)
        float4 av = *(const float4*)&A[(long)(m0 + ar) * lda + k0 + ac4];
        As[ac4 + 0][ar] = av.x;
        As[ac4 + 1][ar] = av.y;
        As[ac4 + 2][ar] = av.z;
        As[ac4 + 3][ar] = av.w;
        if (TRANSB) {
            float4 bv = *(const float4*)&Bm[(long)(n0 + ar) * ldb + k0 + ac4];
            Bs[ac4 + 0][ar] = bv.x;
            Bs[ac4 + 1][ar] = bv.y;
            Bs[ac4 + 2][ar] = bv.z;
            Bs[ac4 + 3][ar] = bv.w;
        } else {
            const int br  = tid >> 4;        // 0..15 (k)
            const int bc4 = (tid & 15) * 4;  // 0..60 (n)
            float4 bv = *(const float4*)&Bm[(long)(k0 + br) * ldb + n0 + bc4];
            *(float4*)&Bs[br][bc4] = bv;
        }
        __syncthreads();

#pragma unroll
        for (int k = 0; k < 16; k++) {
            float4 a = *(const float4*)&As[k][ty * 4];
            float4 b = *(const float4*)&Bs[k][tx * 4];
            float ai[4] = {a.x, a.y, a.z, a.w};
            float bi[4] = {b.x, b.y, b.z, b.w};
#pragma unroll
            for (int i = 0; i < 4; i++)
#pragma unroll
                for (int j = 0; j < 4; j++) acc[i][j] += ai[i] * bi[j];
        }
        __syncthreads();
    }

#pragma unroll
    for (int i = 0; i < 4; i++) {
        const int m = m0 + ty * 4 + i;
#pragma unroll
        for (int j = 0; j < 4; j++) {
            const int n = n0 + tx * 4 + j;
            float v = acc[i][j];
            if (HAS_BIAS) v += bias[n];
            if (HAS_ADD) v += AddB[(long)m * ldc + n];
            if (DO_TANH) v = tanhf(v);
            C[(long)m * ldc + n] = v;
        }
    }
}

// ---------------- emission + masked softmax kernel ----------------
// grid: (QQ/QT, BB), 256 threads. CTA handles QT=4 queries over all C=1024.
// e[q][c] = sum_h tanh(mc[b,c,h] + mq[b,q,h]) * we[h] + we_b ; masked -> -inf
// attn = softmax_c(e), NaN (fully masked) -> 0.
#define QT 4
#define CCHUNK 32

__global__ __launch_bounds__(256)
void emission_softmax_kernel(const float* __restrict__ mc,
                             const float* __restrict__ mq,
                             const int* __restrict__ mask,   // bool input -> int32 words
                             const float* __restrict__ we_w,
                             const float* __restrict__ we_b,
                             float* __restrict__ attn)
{
    __shared__ float mqs[QT][HH];          // 2KB
    __shared__ float wes[HH];              // 512B
    __shared__ float mcs[CCHUNK][HH];      // 16KB
    __shared__ float es[QT][CCN];          // 16KB
    __shared__ int ms[CCHUNK];
    __shared__ float red[256];

    const int b  = blockIdx.y;
    const int q0 = blockIdx.x * QT;
    const int tid = threadIdx.x;
    const int lane = tid & 31;
    const int w    = tid >> 5;   // 8 warps

    if (tid < HH) wes[tid] = we_w[tid];
    for (int i = tid; i < QT * HH; i += 256) {
        int q = i / HH, h = i % HH;
        mqs[q][h] = mq[((long)(b * QQ + q0 + q)) * HH + h];
    }
    __syncthreads();

    const float we_b0 = we_b[0];
    const float4 we4 = *(const float4*)&wes[lane * 4];

    for (int cc = 0; cc < CCN; cc += CCHUNK) {
        __syncthreads();   // protect mcs from previous iteration's readers
        {
            const float4* src = (const float4*)&mc[((long)b * CCN + cc) * HH];
            float4* dst = (float4*)&mcs[0][0];
            for (int i = tid; i < CCHUNK * HH / 4; i += 256) dst[i] = src[i];
            if (tid < CCHUNK) ms[tid] = mask[b * CCN + cc + tid];
        }
        __syncthreads();

        // QT*CCHUNK = 128 (q,c) pairs; warp per pair, lanes over h (4 each)
        for (int p = w; p < QT * CCHUNK; p += 8) {
            const int q = p >> 5;        // p / CCHUNK
            const int c = p & 31;        // p % CCHUNK
            float4 m4 = *(const float4*)&mcs[c][lane * 4];
            float4 q4 = *(const float4*)&mqs[q][lane * 4];
            float s = tanhf(m4.x + q4.x) * we4.x
                    + tanhf(m4.y + q4.y) * we4.y
                    + tanhf(m4.z + q4.z) * we4.z
                    + tanhf(m4.w + q4.w) * we4.w;
#pragma unroll
            for (int off = 16; off >= 1; off >>= 1)
                s += __shfl_xor_sync(0xffffffffu, s, off);
            if (lane == 0)
                es[q][cc + c] = ms[c] ? (s + we_b0) : -INFINITY;
        }
    }
    __syncthreads();

    // softmax per q: 64 threads per query
    const int g = tid >> 6;      // query within tile
    const int t = tid & 63;

    float lm = -INFINITY;
    for (int k = t; k < CCN; k += 64) lm = fmaxf(lm, es[g][k]);
    red[tid] = lm;
    __syncthreads();
#pragma unroll
    for (int s = 32; s >= 1; s >>= 1) {
        if (t < s) red[tid] = fmaxf(red[tid], red[tid + s]);
        __syncthreads();
    }
    const float rmax = red[g << 6];
    const bool ok = (rmax > -3.0e38f);
    __syncthreads();

    float lsum = 0.f;
    for (int k = t; k < CCN; k += 64) {
        float v = es[g][k];
        float e = ok ? __expf(v - rmax) : 0.f;
        es[g][k] = e;
        lsum += e;
    }
    red[tid] = lsum;
    __syncthreads();
#pragma unroll
    for (int s = 32; s >= 1; s >>= 1) {
        if (t < s) red[tid] += red[tid + s];
        __syncthreads();
    }
    const float ssum = red[g << 6];
    const float inv = (ssum > 0.f) ? 1.f / ssum : 0.f;

    float* arow = attn + ((long)(b * QQ + q0 + g)) * CCN;
    for (int k = t; k < CCN; k += 64) arow[k] = es[g][k] * inv;
}

// ---------------- launcher ----------------
extern "C" void kernel_launch(void* const* d_in, const int* in_sizes, int n_in,
                              void* d_out, int out_size)
{
    const float* query   = (const float*)d_in[0];   // (B,Q,QD)
    const float* context = (const float*)d_in[1];   // (B,C,CD)
    const int*   mask    = (const int*)d_in[2];     // (B,C) bool -> int32
    const float* wq_w = (const float*)d_in[3];      // (H,QD)
    const float* wq_b = (const float*)d_in[4];      // (H,)
    const float* wc_w = (const float*)d_in[5];      // (H,CD)
    const float* wc_b = (const float*)d_in[6];      // (H,)
    const float* we_w = (const float*)d_in[7];      // (1,H)
    const float* we_b = (const float*)d_in[8];      // (1,)
    const float* lo_w = (const float*)d_in[9];      // (QD, QD+CD) = (512,1024)
    const float* lo_b = (const float*)d_in[10];     // (QD,)

    float *mc, *mq, *qpart, *wc, *attn_s;
    cudaGetSymbolAddress((void**)&mc, g_mc);
    cudaGetSymbolAddress((void**)&mq, g_mq);
    cudaGetSymbolAddress((void**)&qpart, g_qpart);
    cudaGetSymbolAddress((void**)&wc, g_wc);
    cudaGetSymbolAddress((void**)&attn_s, g_attn_scratch);

    const int nOut  = BB * QQ * QDIM;   // 524288
    const int nAttn = BB * QQ * CCN;    // 1048576
    float* outPtr  = nullptr;
    float* attnPtr = nullptr;
    if (out_size >= nOut + nAttn) {
        outPtr  = (float*)d_out;
        attnPtr = (float*)d_out + nOut;
    } else if (out_size == nAttn) {
        attnPtr = (float*)d_out;
    } else {
        outPtr = (float*)d_out;
    }
    if (!attnPtr) attnPtr = attn_s;

    dim3 blk(256);

    // 1) mc = context @ wc_w.T + wc_b     M=B*C=4096, N=H=128, K=512
    sgemm64<true, true, false, false><<<dim3(HH / 64, BB * CCN / 64, 1), blk>>>(
        context, CDIM, 0, wc_w, CDIM, 0, wc_b, nullptr, mc, HH, 0, CDIM);

    // 2) mq = query @ wq_w.T + wq_b       M=B*Q=1024, N=128, K=512
    sgemm64<true, true, false, false><<<dim3(HH / 64, BB * QQ / 64, 1), blk>>>(
        query, QDIM, 0, wq_w, QDIM, 0, wq_b, nullptr, mq, HH, 0, QDIM);

    // 3) qpart = query @ lo_w[:,512:].T + lo_b   M=1024, N=512, K=512
    sgemm64<true, true, false, false><<<dim3(QDIM / 64, BB * QQ / 64, 1), blk>>>(
        query, QDIM, 0, lo_w + CDIM, QDIM + CDIM, 0, lo_b, nullptr,
        qpart, QDIM, 0, QDIM);

    // 4) emission + softmax -> attn
    emission_softmax_kernel<<<dim3(QQ / QT, BB), blk>>>(mc, mq, mask, we_w, we_b, attnPtr);

    if (outPtr) {
        // 5) wc = attn @ context  (batched over B)  M=256, N=512, K=1024
        sgemm64<false, false, false, false><<<dim3(CDIM / 64, QQ / 64, BB), blk>>>(
            attnPtr, CCN, (long)QQ * CCN,
            context, CDIM, (long)CCN * CDIM,
            nullptr, nullptr,
            wc, CDIM, (long)QQ * CDIM, CCN);

        // 6) out = tanh(wc @ lo_w[:,:512].T + qpart)   M=1024, N=512, K=512
        sgemm64<true, false, true, true><<<dim3(QDIM / 64, BB * QQ / 64, 1), blk>>>(
            wc, CDIM, 0, lo_w, QDIM + CDIM, 0, nullptr, qpart,
            outPtr, QDIM, 0, CDIM);
    }
}

// round 3
// speedup vs baseline: 1.3338x; 1.3338x over previous
#include <cuda_runtime.h>
#include <math.h>

#define BB 4
#define QQ 256
#define CCN 1024
#define QDIM 512
#define CDIM 512
#define HH 128

// ---------------- scratch (device globals; no allocation) ----------------
__device__ float g_mc[BB * CCN * HH];        // (B,C,H)   2MB
__device__ float g_mq[BB * QQ * HH];         // (B,Q,H)   512KB
__device__ float g_qpart[BB * QQ * QDIM];    // (B,Q,QD)  2MB
__device__ float g_wc[BB * QQ * CDIM];       // (B,Q,CD)  2MB
__device__ float g_attn_scratch[BB * QQ * CCN];

// fast tanh: 1 - 2/(e^{2x}+1), via MUFU ex2 + rcp (rel err ~1e-6, branch-free,
// correct saturation at +/-1 for large |x| via inf/0 propagation)
__device__ __forceinline__ float fast_tanh(float x) {
    float e;
    asm("ex2.approx.f32 %0, %1;" : "=f"(e) : "f"(x * 2.8853900817779268f));
    float r;
    asm("rcp.approx.f32 %0, %1;" : "=f"(r) : "f"(e + 1.0f));
    return fmaf(-2.0f, r, 1.0f);
}

// ---------------- generic tiled SGEMM: C = act(A @ op(B) + bias + Add) ----
// A: [M,K] row-major (lda). TRANSB: B is [N,K] (ldb) ; else B is [K,N] (ldb).
// Tile 64x64x16, 256 threads, 4x4 per-thread tile, global->reg prefetch.
template <bool TRANSB, bool HAS_BIAS, bool HAS_ADD, bool DO_TANH>
__global__ __launch_bounds__(256)
void sgemm64(const float* __restrict__ A, int lda, long sA,
             const float* __restrict__ Bm, int ldb, long sB,
             const float* __restrict__ bias,
             const float* __restrict__ Add,
             float* __restrict__ C, int ldc, long sC,
             int K)
{
    __shared__ float As[16][64];
    __shared__ float Bs[16][64];

    const int bz = blockIdx.z;
    A  += (long)bz * sA;
    Bm += (long)bz * sB;
    C  += (long)bz * sC;
    const float* AddB = HAS_ADD ? (Add + (long)bz * sC) : nullptr;

    const int m0 = blockIdx.y * 64;
    const int n0 = blockIdx.x * 64;
    const int tid = threadIdx.x;
    const int tx = tid & 15;       // n
    const int ty = tid >> 4;       // m

    const int ar  = tid >> 2;            // 0..63
    const int ac4 = (tid & 3) * 4;       // 0,4,8,12
    const int br  = tid >> 4;            // 0..15 (k)  (!TRANSB)
    const int bc4 = (tid & 15) * 4;      // 0..60 (n)  (!TRANSB)

    float acc[4][4];
#pragma unroll
    for (int i = 0; i < 4; i++)
#pragma unroll
        for (int j = 0; j < 4; j++) acc[i][j] = 0.f;

    // prefetch first tile
    float4 av = *(const float4*)&A[(long)(m0 + ar) * lda + ac4];
    float4 bv = TRANSB ? *(const float4*)&Bm[(long)(n0 + ar) * ldb + ac4]
                       : *(const float4*)&Bm[(long)br * ldb + n0 + bc4];

    for (int k0 = 0; k0 < K; k0 += 16) {
        // store current tile to smem
        As[ac4 + 0][ar] = av.x;
        As[ac4 + 1][ar] = av.y;
        As[ac4 + 2][ar] = av.z;
        As[ac4 + 3][ar] = av.w;
        if (TRANSB) {
            Bs[ac4 + 0][ar] = bv.x;
            Bs[ac4 + 1][ar] = bv.y;
            Bs[ac4 + 2][ar] = bv.z;
            Bs[ac4 + 3][ar] = bv.w;
        } else {
            *(float4*)&Bs[br][bc4] = bv;
        }
        __syncthreads();

        // prefetch next tile while computing
        if (k0 + 16 < K) {
            av = *(const float4*)&A[(long)(m0 + ar) * lda + (k0 + 16) + ac4];
            bv = TRANSB ? *(const float4*)&Bm[(long)(n0 + ar) * ldb + (k0 + 16) + ac4]
                        : *(const float4*)&Bm[(long)(k0 + 16 + br) * ldb + n0 + bc4];
        }

#pragma unroll
        for (int k = 0; k < 16; k++) {
            float4 a = *(const float4*)&As[k][ty * 4];
            float4 b = *(const float4*)&Bs[k][tx * 4];
            float ai[4] = {a.x, a.y, a.z, a.w};
            float bi[4] = {b.x, b.y, b.z, b.w};
#pragma unroll
            for (int i = 0; i < 4; i++)
#pragma unroll
                for (int j = 0; j < 4; j++) acc[i][j] += ai[i] * bi[j];
        }
        __syncthreads();
    }

#pragma unroll
    for (int i = 0; i < 4; i++) {
        const int m = m0 + ty * 4 + i;
#pragma unroll
        for (int j = 0; j < 4; j++) {
            const int n = n0 + tx * 4 + j;
            float v = acc[i][j];
            if (HAS_BIAS) v += bias[n];
            if (HAS_ADD) v += AddB[(long)m * ldc + n];
            if (DO_TANH) v = fast_tanh(v);
            C[(long)m * ldc + n] = v;
        }
    }
}

// ---------------- emission + masked softmax kernel ----------------
// grid: (QQ/QT, BB), 256 threads. CTA handles QT=2 queries over C=1024.
#define QT 2
#define CCHUNK 32

__global__ __launch_bounds__(256)
void emission_softmax_kernel(const float* __restrict__ mc,
                             const float* __restrict__ mq,
                             const int* __restrict__ mask,   // bool -> int32
                             const float* __restrict__ we_w,
                             const float* __restrict__ we_b,
                             float* __restrict__ attn)
{
    __shared__ float mqs[QT][HH];          // 1KB
    __shared__ float wes[HH];              // 512B
    __shared__ float mcs[CCHUNK][HH];      // 16KB
    __shared__ float es[QT][CCN];          // 8KB
    __shared__ int ms[CCHUNK];
    __shared__ float red[256];

    const int b  = blockIdx.y;
    const int q0 = blockIdx.x * QT;
    const int tid = threadIdx.x;
    const int lane = tid & 31;
    const int w    = tid >> 5;   // 8 warps

    if (tid < HH) wes[tid] = we_w[tid];
    for (int i = tid; i < QT * HH; i += 256) {
        int q = i / HH, h = i % HH;
        mqs[q][h] = mq[((long)(b * QQ + q0 + q)) * HH + h];
    }
    __syncthreads();

    const float we_b0 = we_b[0];
    const float4 we4 = *(const float4*)&wes[lane * 4];
    const float4 mq0 = *(const float4*)&mqs[0][lane * 4];
    const float4 mq1 = *(const float4*)&mqs[1][lane * 4];

    for (int cc = 0; cc < CCN; cc += CCHUNK) {
        __syncthreads();   // protect mcs from previous iteration's readers
        {
            const float4* src = (const float4*)&mc[((long)b * CCN + cc) * HH];
            float4* dst = (float4*)&mcs[0][0];
            for (int i = tid; i < CCHUNK * HH / 4; i += 256) dst[i] = src[i];
            if (tid < CCHUNK) ms[tid] = mask[b * CCN + cc + tid];
        }
        __syncthreads();

        // QT*CCHUNK = 64 pairs; warp per (q,c) pair, lanes over h (4 each)
        for (int p = w; p < QT * CCHUNK; p += 8) {
            const int q = p >> 5;
            const int c = p & 31;
            float4 m4 = *(const float4*)&mcs[c][lane * 4];
            float4 q4 = q ? mq1 : mq0;
            float s = fast_tanh(m4.x + q4.x) * we4.x
                    + fast_tanh(m4.y + q4.y) * we4.y
                    + fast_tanh(m4.z + q4.z) * we4.z
                    + fast_tanh(m4.w + q4.w) * we4.w;
#pragma unroll
            for (int off = 16; off >= 1; off >>= 1)
                s += __shfl_xor_sync(0xffffffffu, s, off);
            if (lane == 0)
                es[q][cc + c] = ms[c] ? (s + we_b0) : -INFINITY;
        }
    }
    __syncthreads();

    // softmax per q: 128 threads per query
    const int g = tid >> 7;
    const int t = tid & 127;

    float lm = -INFINITY;
    for (int k = t; k < CCN; k += 128) lm = fmaxf(lm, es[g][k]);
    red[tid] = lm;
    __syncthreads();
#pragma unroll
    for (int s = 64; s >= 1; s >>= 1) {
        if (t < s) red[tid] = fmaxf(red[tid], red[tid + s]);
        __syncthreads();
    }
    const float rmax = red[g << 7];
    const bool ok = (rmax > -3.0e38f);
    __syncthreads();

    float lsum = 0.f;
    for (int k = t; k < CCN; k += 128) {
        float v = es[g][k];
        float e = ok ? __expf(v - rmax) : 0.f;
        es[g][k] = e;
        lsum += e;
    }
    red[tid] = lsum;
    __syncthreads();
#pragma unroll
    for (int s = 64; s >= 1; s >>= 1) {
        if (t < s) red[tid] += red[tid + s];
        __syncthreads();
    }
    const float ssum = red[g << 7];
    const float inv = (ssum > 0.f) ? 1.f / ssum : 0.f;

    float* arow = attn + ((long)(b * QQ + q0 + g)) * CCN;
    for (int k = t; k < CCN; k += 128) arow[k] = es[g][k] * inv;
}

// ---------------- launcher ----------------
extern "C" void kernel_launch(void* const* d_in, const int* in_sizes, int n_in,
                              void* d_out, int out_size)
{
    const float* query   = (const float*)d_in[0];   // (B,Q,QD)
    const float* context = (const float*)d_in[1];   // (B,C,CD)
    const int*   mask    = (const int*)d_in[2];     // (B,C) bool -> int32
    const float* wq_w = (const float*)d_in[3];      // (H,QD)
    const float* wq_b = (const float*)d_in[4];      // (H,)
    const float* wc_w = (const float*)d_in[5];      // (H,CD)
    const float* wc_b = (const float*)d_in[6];      // (H,)
    const float* we_w = (const float*)d_in[7];      // (1,H)
    const float* we_b = (const float*)d_in[8];      // (1,)
    const float* lo_w = (const float*)d_in[9];      // (QD, QD+CD)
    const float* lo_b = (const float*)d_in[10];     // (QD,)

    float *mc, *mq, *qpart, *wc, *attn_s;
    cudaGetSymbolAddress((void**)&mc, g_mc);
    cudaGetSymbolAddress((void**)&mq, g_mq);
    cudaGetSymbolAddress((void**)&qpart, g_qpart);
    cudaGetSymbolAddress((void**)&wc, g_wc);
    cudaGetSymbolAddress((void**)&attn_s, g_attn_scratch);

    const int nOut  = BB * QQ * QDIM;   // 524288
    const int nAttn = BB * QQ * CCN;    // 1048576
    float* outPtr  = nullptr;
    float* attnPtr = nullptr;
    if (out_size >= nOut + nAttn) {
        outPtr  = (float*)d_out;
        attnPtr = (float*)d_out + nOut;
    } else if (out_size == nAttn) {
        attnPtr = (float*)d_out;
    } else {
        outPtr = (float*)d_out;
    }
    if (!attnPtr) attnPtr = attn_s;

    dim3 blk(256);

    // 1) mc = context @ wc_w.T + wc_b     M=4096, N=128, K=512
    sgemm64<true, true, false, false><<<dim3(HH / 64, BB * CCN / 64, 1), blk>>>(
        context, CDIM, 0, wc_w, CDIM, 0, wc_b, nullptr, mc, HH, 0, CDIM);

    // 2) mq = query @ wq_w.T + wq_b       M=1024, N=128, K=512
    sgemm64<true, true, false, false><<<dim3(HH / 64, BB * QQ / 64, 1), blk>>>(
        query, QDIM, 0, wq_w, QDIM, 0, wq_b, nullptr, mq, HH, 0, QDIM);

    // 3) qpart = query @ lo_w[:,512:].T + lo_b   M=1024, N=512, K=512
    sgemm64<true, true, false, false><<<dim3(QDIM / 64, BB * QQ / 64, 1), blk>>>(
        query, QDIM, 0, lo_w + CDIM, QDIM + CDIM, 0, lo_b, nullptr,
        qpart, QDIM, 0, QDIM);

    // 4) emission + softmax -> attn
    emission_softmax_kernel<<<dim3(QQ / QT, BB), blk>>>(mc, mq, mask, we_w, we_b, attnPtr);

    if (outPtr) {
        // 5) wc = attn @ context  (batched over B)  M=256, N=512, K=1024
        sgemm64<false, false, false, false><<<dim3(CDIM / 64, QQ / 64, BB), blk>>>(
            attnPtr, CCN, (long)QQ * CCN,
            context, CDIM, (long)CCN * CDIM,
            nullptr, nullptr,
            wc, CDIM, (long)QQ * CDIM, CCN);

        // 6) out = tanh(wc @ lo_w[:,:512].T + qpart)   M=1024, N=512, K=512
        sgemm64<true, false, true, true><<<dim3(QDIM / 64, BB * QQ / 64, 1), blk>>>(
            wc, CDIM, 0, lo_w, QDIM + CDIM, 0, nullptr, qpart,
            outPtr, QDIM, 0, CDIM);
    }
}

// round 4
// speedup vs baseline: 1.8818x; 1.4108x over previous
#include <cuda_runtime.h>
#include <math.h>

#define BB 4
#define QQ 256
#define CCN 1024
#define QDIM 512
#define CDIM 512
#define HH 128

// ---------------- scratch (device globals; no allocation) ----------------
__device__ float g_Ec[BB * CCN * HH];        // e^{2*mc}  (B,C,H) 2MB
__device__ float g_Eq[BB * QQ * HH];         // e^{2*mq}  (B,Q,H) 512KB
__device__ float g_qpart[BB * QQ * QDIM];    // query @ lo_w[:,512:].T + lo_b
__device__ float g_wc[BB * QQ * CDIM];       // attn @ context
__device__ float g_attn_scratch[BB * QQ * CCN];

#define TWO_LOG2E 2.8853900817779268f

__device__ __forceinline__ float fast_ex2(float x) {
    float e; asm("ex2.approx.f32 %0, %1;" : "=f"(e) : "f"(x)); return e;
}
__device__ __forceinline__ float fast_rcp(float x) {
    float r; asm("rcp.approx.f32 %0, %1;" : "=f"(r) : "f"(x)); return r;
}
// tanh(x) = 1 - 2/(e^{2x}+1): rel err ~1e-6, saturates correctly
__device__ __forceinline__ float fast_tanh(float x) {
    float e = fast_ex2(x * TWO_LOG2E);
    return fmaf(-2.0f, fast_rcp(e + 1.0f), 1.0f);
}

// ---------------- generic tiled SGEMM: C = act(A @ op(B) + bias + Add) ----
template <bool TRANSB, bool HAS_BIAS, bool HAS_ADD, bool DO_TANH>
__global__ __launch_bounds__(256)
void sgemm64(const float* __restrict__ A, int lda, long sA,
             const float* __restrict__ Bm, int ldb, long sB,
             const float* __restrict__ bias,
             const float* __restrict__ Add,
             float* __restrict__ C, int ldc, long sC,
             int K)
{
    __shared__ float As[16][64];
    __shared__ float Bs[16][64];

    const int bz = blockIdx.z;
    A  += (long)bz * sA;
    Bm += (long)bz * sB;
    C  += (long)bz * sC;
    const float* AddB = HAS_ADD ? (Add + (long)bz * sC) : nullptr;

    const int m0 = blockIdx.y * 64;
    const int n0 = blockIdx.x * 64;
    const int tid = threadIdx.x;
    const int tx = tid & 15;
    const int ty = tid >> 4;

    const int ar  = tid >> 2;
    const int ac4 = (tid & 3) * 4;
    const int br  = tid >> 4;
    const int bc4 = (tid & 15) * 4;

    float acc[4][4];
#pragma unroll
    for (int i = 0; i < 4; i++)
#pragma unroll
        for (int j = 0; j < 4; j++) acc[i][j] = 0.f;

    float4 av = *(const float4*)&A[(long)(m0 + ar) * lda + ac4];
    float4 bv = TRANSB ? *(const float4*)&Bm[(long)(n0 + ar) * ldb + ac4]
                       : *(const float4*)&Bm[(long)br * ldb + n0 + bc4];

    for (int k0 = 0; k0 < K; k0 += 16) {
        As[ac4 + 0][ar] = av.x;
        As[ac4 + 1][ar] = av.y;
        As[ac4 + 2][ar] = av.z;
        As[ac4 + 3][ar] = av.w;
        if (TRANSB) {
            Bs[ac4 + 0][ar] = bv.x;
            Bs[ac4 + 1][ar] = bv.y;
            Bs[ac4 + 2][ar] = bv.z;
            Bs[ac4 + 3][ar] = bv.w;
        } else {
            *(float4*)&Bs[br][bc4] = bv;
        }
        __syncthreads();

        if (k0 + 16 < K) {
            av = *(const float4*)&A[(long)(m0 + ar) * lda + (k0 + 16) + ac4];
            bv = TRANSB ? *(const float4*)&Bm[(long)(n0 + ar) * ldb + (k0 + 16) + ac4]
                        : *(const float4*)&Bm[(long)(k0 + 16 + br) * ldb + n0 + bc4];
        }

#pragma unroll
        for (int k = 0; k < 16; k++) {
            float4 a = *(const float4*)&As[k][ty * 4];
            float4 b = *(const float4*)&Bs[k][tx * 4];
            float ai[4] = {a.x, a.y, a.z, a.w};
            float bi[4] = {b.x, b.y, b.z, b.w};
#pragma unroll
            for (int i = 0; i < 4; i++)
#pragma unroll
                for (int j = 0; j < 4; j++) acc[i][j] += ai[i] * bi[j];
        }
        __syncthreads();
    }

#pragma unroll
    for (int i = 0; i < 4; i++) {
        const int m = m0 + ty * 4 + i;
#pragma unroll
        for (int j = 0; j < 4; j++) {
            const int n = n0 + tx * 4 + j;
            float v = acc[i][j];
            if (HAS_BIAS) v += bias[n];
            if (HAS_ADD) v += AddB[(long)m * ldc + n];
            if (DO_TANH) v = fast_tanh(v);
            C[(long)m * ldc + n] = v;
        }
    }
}

// ---------------- fused projection: Ec = exp(2*(context@wcT+wcb)), Eq likewise
// One launch: blockIdx.y < 64 -> context rows (4096), else query rows (1024).
// N = 128, K = 512, TRANSB, bias, exp epilogue. 160 CTAs = one full wave.
__global__ __launch_bounds__(256)
void proj12_kernel(const float* __restrict__ context,
                   const float* __restrict__ query,
                   const float* __restrict__ wc_w, const float* __restrict__ wc_b,
                   const float* __restrict__ wq_w, const float* __restrict__ wq_b,
                   float* __restrict__ Ec, float* __restrict__ Eq)
{
    __shared__ float As[16][64];
    __shared__ float Bs[16][64];

    const bool isQ = blockIdx.y >= (BB * CCN / 64);
    const float* A   = isQ ? query : context;
    const float* Bm  = isQ ? wq_w : wc_w;
    const float* bias= isQ ? wq_b : wc_b;
    float* C         = isQ ? Eq : Ec;
    const int m0 = (isQ ? (blockIdx.y - BB * CCN / 64) : blockIdx.y) * 64;
    const int n0 = blockIdx.x * 64;
    const int K = 512;

    const int tid = threadIdx.x;
    const int tx = tid & 15;
    const int ty = tid >> 4;
    const int ar  = tid >> 2;
    const int ac4 = (tid & 3) * 4;

    float acc[4][4];
#pragma unroll
    for (int i = 0; i < 4; i++)
#pragma unroll
        for (int j = 0; j < 4; j++) acc[i][j] = 0.f;

    float4 av = *(const float4*)&A[(long)(m0 + ar) * K + ac4];
    float4 bv = *(const float4*)&Bm[(long)(n0 + ar) * K + ac4];

    for (int k0 = 0; k0 < K; k0 += 16) {
        As[ac4 + 0][ar] = av.x; As[ac4 + 1][ar] = av.y;
        As[ac4 + 2][ar] = av.z; As[ac4 + 3][ar] = av.w;
        Bs[ac4 + 0][ar] = bv.x; Bs[ac4 + 1][ar] = bv.y;
        Bs[ac4 + 2][ar] = bv.z; Bs[ac4 + 3][ar] = bv.w;
        __syncthreads();

        if (k0 + 16 < K) {
            av = *(const float4*)&A[(long)(m0 + ar) * K + (k0 + 16) + ac4];
            bv = *(const float4*)&Bm[(long)(n0 + ar) * K + (k0 + 16) + ac4];
        }

#pragma unroll
        for (int k = 0; k < 16; k++) {
            float4 a = *(const float4*)&As[k][ty * 4];
            float4 b = *(const float4*)&Bs[k][tx * 4];
            float ai[4] = {a.x, a.y, a.z, a.w};
            float bi[4] = {b.x, b.y, b.z, b.w};
#pragma unroll
            for (int i = 0; i < 4; i++)
#pragma unroll
                for (int j = 0; j < 4; j++) acc[i][j] += ai[i] * bi[j];
        }
        __syncthreads();
    }

#pragma unroll
    for (int i = 0; i < 4; i++) {
        const int m = m0 + ty * 4 + i;
#pragma unroll
        for (int j = 0; j < 4; j++) {
            const int n = n0 + tx * 4 + j;
            float v = acc[i][j] + bias[n];
            C[(long)m * HH + n] = fast_ex2(v * TWO_LOG2E);
        }
    }
}

// ---------------- emission + masked softmax ----------------
// tanh-sum = W - 2*sum_h we_h / (1 + Ec*Eq);  emission = tanh-sum + we_b
// CTA: (b, 4 queries). 128 threads: warp = query, lane = c-within-chunk.
// es kept in registers (32 per thread); softmax = one warp reduce.
#define QT 4
#define CH 32
#define NCHUNK (CCN / CH)    // 32
#define ECPAD 132            // stride 132 floats: conflict-free lane-major LDS.128

__global__ __launch_bounds__(128)
void emission_softmax2(const float* __restrict__ Ec,
                       const float* __restrict__ Eq,
                       const int* __restrict__ mask,
                       const float* __restrict__ we_w,
                       const float* __restrict__ we_b,
                       float* __restrict__ attn)
{
    __shared__ float ecs[CH][ECPAD];   // ~16.9KB
    __shared__ float eqs[QT][HH];      // 2KB
    __shared__ float wes[HH];          // 512B
    __shared__ int ms[CH];

    const int b  = blockIdx.y;
    const int q0 = blockIdx.x * QT;
    const int tid = threadIdx.x;
    const int lane = tid & 31;
    const int q = tid >> 5;            // warp id = query in tile

    if (tid < HH) wes[tid] = we_w[tid];
    {
        const float4* src = (const float4*)&Eq[(long)(b * QQ + q0) * HH];
        float4* dst = (float4*)&eqs[0][0];
        for (int i = tid; i < QT * HH / 4; i += 128) dst[i] = src[i];
    }
    __syncthreads();

    float W = 0.f;
#pragma unroll
    for (int h = 0; h < HH; h += 4) {
        float4 w4 = *(const float4*)&wes[h];
        W += (w4.x + w4.y) + (w4.z + w4.w);
    }
    const float eb = we_b[0];

    float es_l[NCHUNK];

    for (int ch = 0; ch < NCHUNK; ch++) {
        __syncthreads();
        {
            const float4* src = (const float4*)&Ec[((long)b * CCN + ch * CH) * HH];
            for (int i = tid; i < CH * HH / 4; i += 128) {
                int r  = i >> 5;            // i / 32  (32 float4 per row)
                int c4 = (i & 31) * 4;
                *(float4*)&ecs[r][c4] = src[i];
            }
            if (tid < CH) ms[tid] = mask[b * CCN + ch * CH + tid];
        }
        __syncthreads();

        float s0 = 0.f, s1 = 0.f;
#pragma unroll
        for (int h = 0; h < HH; h += 8) {
            float4 e0 = *(const float4*)&ecs[lane][h];
            float4 g0 = *(const float4*)&eqs[q][h];
            float4 w0 = *(const float4*)&wes[h];
            float4 e1 = *(const float4*)&ecs[lane][h + 4];
            float4 g1 = *(const float4*)&eqs[q][h + 4];
            float4 w1 = *(const float4*)&wes[h + 4];
            s0 += w0.x * fast_rcp(fmaf(e0.x, g0.x, 1.f));
            s1 += w0.y * fast_rcp(fmaf(e0.y, g0.y, 1.f));
            s0 += w0.z * fast_rcp(fmaf(e0.z, g0.z, 1.f));
            s1 += w0.w * fast_rcp(fmaf(e0.w, g0.w, 1.f));
            s0 += w1.x * fast_rcp(fmaf(e1.x, g1.x, 1.f));
            s1 += w1.y * fast_rcp(fmaf(e1.y, g1.y, 1.f));
            s0 += w1.z * fast_rcp(fmaf(e1.z, g1.z, 1.f));
            s1 += w1.w * fast_rcp(fmaf(e1.w, g1.w, 1.f));
        }
        float s = s0 + s1;
        es_l[ch] = ms[lane] ? (fmaf(-2.f, s, W) + eb) : -INFINITY;
    }

    // softmax across the warp's 1024 values
    float lm = -INFINITY;
#pragma unroll
    for (int ch = 0; ch < NCHUNK; ch++) lm = fmaxf(lm, es_l[ch]);
#pragma unroll
    for (int off = 16; off >= 1; off >>= 1)
        lm = fmaxf(lm, __shfl_xor_sync(0xffffffffu, lm, off));
    const bool ok = (lm > -3.0e38f);

    float ls = 0.f;
#pragma unroll
    for (int ch = 0; ch < NCHUNK; ch++) {
        float e = ok ? __expf(es_l[ch] - lm) : 0.f;
        es_l[ch] = e;
        ls += e;
    }
#pragma unroll
    for (int off = 16; off >= 1; off >>= 1)
        ls += __shfl_xor_sync(0xffffffffu, ls, off);
    const float inv = (ls > 0.f) ? 1.f / ls : 0.f;

    float* arow = attn + (long)(b * QQ + q0 + q) * CCN;
#pragma unroll
    for (int ch = 0; ch < NCHUNK; ch++) arow[ch * CH + lane] = es_l[ch] * inv;
}

// ---------------- launcher ----------------
extern "C" void kernel_launch(void* const* d_in, const int* in_sizes, int n_in,
                              void* d_out, int out_size)
{
    const float* query   = (const float*)d_in[0];
    const float* context = (const float*)d_in[1];
    const int*   mask    = (const int*)d_in[2];
    const float* wq_w = (const float*)d_in[3];
    const float* wq_b = (const float*)d_in[4];
    const float* wc_w = (const float*)d_in[5];
    const float* wc_b = (const float*)d_in[6];
    const float* we_w = (const float*)d_in[7];
    const float* we_b = (const float*)d_in[8];
    const float* lo_w = (const float*)d_in[9];
    const float* lo_b = (const float*)d_in[10];

    float *Ec, *Eq, *qpart, *wc, *attn_s;
    cudaGetSymbolAddress((void**)&Ec, g_Ec);
    cudaGetSymbolAddress((void**)&Eq, g_Eq);
    cudaGetSymbolAddress((void**)&qpart, g_qpart);
    cudaGetSymbolAddress((void**)&wc, g_wc);
    cudaGetSymbolAddress((void**)&attn_s, g_attn_scratch);

    const int nOut  = BB * QQ * QDIM;
    const int nAttn = BB * QQ * CCN;
    float* outPtr  = nullptr;
    float* attnPtr = nullptr;
    if (out_size >= nOut + nAttn) {
        outPtr  = (float*)d_out;
        attnPtr = (float*)d_out + nOut;
    } else if (out_size == nAttn) {
        attnPtr = (float*)d_out;
    } else {
        outPtr = (float*)d_out;
    }
    if (!attnPtr) attnPtr = attn_s;

    dim3 blk(256);

    // 1+2) Ec/Eq projections fused: 160 CTAs
    proj12_kernel<<<dim3(HH / 64, BB * CCN / 64 + BB * QQ / 64), blk>>>(
        context, query, wc_w, wc_b, wq_w, wq_b, Ec, Eq);

    // 3) emission + softmax -> attn
    emission_softmax2<<<dim3(QQ / QT, BB), 128>>>(Ec, Eq, mask, we_w, we_b, attnPtr);

    // 4) qpart = query @ lo_w[:,512:].T + lo_b
    sgemm64<true, true, false, false><<<dim3(QDIM / 64, BB * QQ / 64, 1), blk>>>(
        query, QDIM, 0, lo_w + CDIM, QDIM + CDIM, 0, lo_b, nullptr,
        qpart, QDIM, 0, QDIM);

    if (outPtr) {
        // 5) wc = attn @ context (batched over B)
        sgemm64<false, false, false, false><<<dim3(CDIM / 64, QQ / 64, BB), blk>>>(
            attnPtr, CCN, (long)QQ * CCN,
            context, CDIM, (long)CCN * CDIM,
            nullptr, nullptr,
            wc, CDIM, (long)QQ * CDIM, CCN);

        // 6) out = tanh(wc @ lo_w[:,:512].T + qpart)
        sgemm64<true, false, true, true><<<dim3(QDIM / 64, BB * QQ / 64, 1), blk>>>(
            wc, CDIM, 0, lo_w, QDIM + CDIM, 0, nullptr, qpart,
            outPtr, QDIM, 0, CDIM);
    }
}

// round 5
// speedup vs baseline: 2.1091x; 1.1208x over previous
#include <cuda_runtime.h>
#include <math.h>

#define BB 4
#define QQ 256
#define CCN 1024
#define QDIM 512
#define CDIM 512
#define HH 128

// ---------------- scratch (device globals; no allocation) ----------------
__device__ float g_Ec[BB * CCN * HH];        // e^{2*mc}  (B,C,H)
__device__ float g_Eq[BB * QQ * HH];         // e^{2*mq}  (B,Q,H)
__device__ float g_qpart[BB * QQ * QDIM];    // query @ lo_w[:,512:].T + lo_b
__device__ float g_wc[BB * QQ * CDIM];       // attn @ context
__device__ float g_attn_scratch[BB * QQ * CCN];

#define TWO_LOG2E 2.8853900817779268f

__device__ __forceinline__ float fast_ex2(float x) {
    float e; asm("ex2.approx.f32 %0, %1;" : "=f"(e) : "f"(x)); return e;
}
__device__ __forceinline__ float fast_rcp(float x) {
    float r; asm("rcp.approx.f32 %0, %1;" : "=f"(r) : "f"(x)); return r;
}
__device__ __forceinline__ float fast_tanh(float x) {
    float e = fast_ex2(x * TWO_LOG2E);
    return fmaf(-2.0f, fast_rcp(e + 1.0f), 1.0f);
}

// ---------------- 32x64x16 GEMM core, 128 threads, double-buffered ----------
// A: [M,K] row-major (lda). TRANSB: B is [N,K] (ldb); else [K,N] (ldb).
// epi: 0 = none, 1 = ex2(2*log2e*v), 2 = fast_tanh(v)
template <bool TRANSB>
__device__ __forceinline__
void gemm32(const float* __restrict__ A, int lda,
            const float* __restrict__ Bm, int ldb,
            const float* __restrict__ bias,      // nullable
            const float* __restrict__ Add,       // nullable, ldc layout
            float* __restrict__ C, int ldc,
            int K, int m0, int n0, int epi)
{
    __shared__ float As[2][16][32];
    __shared__ float Bs[2][16][64];

    const int tid = threadIdx.x;
    const int tx  = tid & 15;        // n group (x4)
    const int tyr = tid >> 4;        // 0..7 m group (x4)

    const int ar  = tid >> 2;        // 0..31
    const int ac4 = (tid & 3) * 4;   // k sub

    float acc[4][4];
#pragma unroll
    for (int i = 0; i < 4; i++)
#pragma unroll
        for (int j = 0; j < 4; j++) acc[i][j] = 0.f;

    // prefetch tile 0
    float4 av, bv0, bv1;
    av = *(const float4*)&A[(long)(m0 + ar) * lda + ac4];
    if (TRANSB) {
        bv0 = *(const float4*)&Bm[(long)(n0 + ar) * ldb + ac4];
        bv1 = *(const float4*)&Bm[(long)(n0 + 32 + ar) * ldb + ac4];
    } else {
        bv0 = *(const float4*)&Bm[(long)(tid >> 4) * ldb + n0 + (tid & 15) * 4];
        bv1 = *(const float4*)&Bm[(long)(8 + (tid >> 4)) * ldb + n0 + (tid & 15) * 4];
    }

    // store tile 0
    As[0][ac4 + 0][ar] = av.x; As[0][ac4 + 1][ar] = av.y;
    As[0][ac4 + 2][ar] = av.z; As[0][ac4 + 3][ar] = av.w;
    if (TRANSB) {
        Bs[0][ac4 + 0][ar] = bv0.x; Bs[0][ac4 + 1][ar] = bv0.y;
        Bs[0][ac4 + 2][ar] = bv0.z; Bs[0][ac4 + 3][ar] = bv0.w;
        Bs[0][ac4 + 0][32 + ar] = bv1.x; Bs[0][ac4 + 1][32 + ar] = bv1.y;
        Bs[0][ac4 + 2][32 + ar] = bv1.z; Bs[0][ac4 + 3][32 + ar] = bv1.w;
    } else {
        *(float4*)&Bs[0][tid >> 4][(tid & 15) * 4] = bv0;
        *(float4*)&Bs[0][8 + (tid >> 4)][(tid & 15) * 4] = bv1;
    }
    __syncthreads();

    int cur = 0;
    for (int k0 = 0; k0 < K; k0 += 16) {
        const bool more = (k0 + 16) < K;
        if (more) {
            const int kn = k0 + 16;
            av = *(const float4*)&A[(long)(m0 + ar) * lda + kn + ac4];
            if (TRANSB) {
                bv0 = *(const float4*)&Bm[(long)(n0 + ar) * ldb + kn + ac4];
                bv1 = *(const float4*)&Bm[(long)(n0 + 32 + ar) * ldb + kn + ac4];
            } else {
                bv0 = *(const float4*)&Bm[(long)(kn + (tid >> 4)) * ldb + n0 + (tid & 15) * 4];
                bv1 = *(const float4*)&Bm[(long)(kn + 8 + (tid >> 4)) * ldb + n0 + (tid & 15) * 4];
            }
        }

#pragma unroll
        for (int k = 0; k < 16; k++) {
            float4 a = *(const float4*)&As[cur][k][tyr * 4];
            float4 b = *(const float4*)&Bs[cur][k][tx * 4];
            float ai[4] = {a.x, a.y, a.z, a.w};
            float bi[4] = {b.x, b.y, b.z, b.w};
#pragma unroll
            for (int i = 0; i < 4; i++)
#pragma unroll
                for (int j = 0; j < 4; j++) acc[i][j] += ai[i] * bi[j];
        }

        if (more) {
            const int nxt = cur ^ 1;
            As[nxt][ac4 + 0][ar] = av.x; As[nxt][ac4 + 1][ar] = av.y;
            As[nxt][ac4 + 2][ar] = av.z; As[nxt][ac4 + 3][ar] = av.w;
            if (TRANSB) {
                Bs[nxt][ac4 + 0][ar] = bv0.x; Bs[nxt][ac4 + 1][ar] = bv0.y;
                Bs[nxt][ac4 + 2][ar] = bv0.z; Bs[nxt][ac4 + 3][ar] = bv0.w;
                Bs[nxt][ac4 + 0][32 + ar] = bv1.x; Bs[nxt][ac4 + 1][32 + ar] = bv1.y;
                Bs[nxt][ac4 + 2][32 + ar] = bv1.z; Bs[nxt][ac4 + 3][32 + ar] = bv1.w;
            } else {
                *(float4*)&Bs[nxt][tid >> 4][(tid & 15) * 4] = bv0;
                *(float4*)&Bs[nxt][8 + (tid >> 4)][(tid & 15) * 4] = bv1;
            }
        }
        __syncthreads();
        cur ^= 1;
    }

    // epilogue: float4 stores over n
    const int nb = n0 + tx * 4;
    float4 b4 = bias ? *(const float4*)&bias[nb] : make_float4(0.f, 0.f, 0.f, 0.f);
#pragma unroll
    for (int i = 0; i < 4; i++) {
        const int m = m0 + tyr * 4 + i;
        float4 v = make_float4(acc[i][0] + b4.x, acc[i][1] + b4.y,
                               acc[i][2] + b4.z, acc[i][3] + b4.w);
        if (Add) {
            float4 a4 = *(const float4*)&Add[(long)m * ldc + nb];
            v.x += a4.x; v.y += a4.y; v.z += a4.z; v.w += a4.w;
        }
        if (epi == 1) {
            v.x = fast_ex2(v.x * TWO_LOG2E); v.y = fast_ex2(v.y * TWO_LOG2E);
            v.z = fast_ex2(v.z * TWO_LOG2E); v.w = fast_ex2(v.w * TWO_LOG2E);
        } else if (epi == 2) {
            v.x = fast_tanh(v.x); v.y = fast_tanh(v.y);
            v.z = fast_tanh(v.z); v.w = fast_tanh(v.w);
        }
        *(float4*)&C[(long)m * ldc + nb] = v;
    }
}

// ---------------- fused input projections: Ec, Eq, qpart (576 CTAs) --------
__global__ __launch_bounds__(128)
void proj_fused_kernel(const float* __restrict__ context,
                       const float* __restrict__ query,
                       const float* __restrict__ wc_w, const float* __restrict__ wc_b,
                       const float* __restrict__ wq_w, const float* __restrict__ wq_b,
                       const float* __restrict__ lo_w, const float* __restrict__ lo_b,
                       float* __restrict__ Ec, float* __restrict__ Eq,
                       float* __restrict__ qpart)
{
    const int i = blockIdx.x;
    if (i < 256) {               // Ec: 128 m-tiles x 2 n-tiles
        const int m0 = (i >> 1) * 32, n0 = (i & 1) * 64;
        gemm32<true>(context, CDIM, wc_w, CDIM, wc_b, nullptr, Ec, HH,
                     CDIM, m0, n0, 1);
    } else if (i < 320) {        // Eq: 32 x 2
        const int j = i - 256;
        const int m0 = (j >> 1) * 32, n0 = (j & 1) * 64;
        gemm32<true>(query, QDIM, wq_w, QDIM, wq_b, nullptr, Eq, HH,
                     QDIM, m0, n0, 1);
    } else {                     // qpart: 32 x 8
        const int j = i - 320;
        const int m0 = (j >> 3) * 32, n0 = (j & 7) * 64;
        gemm32<true>(query, QDIM, lo_w + CDIM, QDIM + CDIM, lo_b, nullptr,
                     qpart, QDIM, QDIM, m0, n0, 0);
    }
}

// ---------------- wc = attn @ context (256 CTAs) ---------------------------
__global__ __launch_bounds__(128)
void gemm_nn_kernel(const float* __restrict__ attn,
                    const float* __restrict__ context,
                    float* __restrict__ wc)
{
    const int b = blockIdx.z;
    gemm32<false>(attn + (long)b * QQ * CCN, CCN,
                  context + (long)b * CCN * CDIM, CDIM,
                  nullptr, nullptr,
                  wc + (long)b * QQ * CDIM, CDIM,
                  CCN, blockIdx.y * 32, blockIdx.x * 64, 0);
}

// ---------------- out = tanh(wc @ lo_w[:,:512].T + qpart) (256 CTAs) -------
__global__ __launch_bounds__(128)
void gemm_out_kernel(const float* __restrict__ wc,
                     const float* __restrict__ lo_w,
                     const float* __restrict__ qpart,
                     float* __restrict__ out)
{
    gemm32<true>(wc, CDIM, lo_w, QDIM + CDIM, nullptr, qpart,
                 out, QDIM, CDIM, blockIdx.y * 32, blockIdx.x * 64, 2);
}

// ---------------- emission + masked softmax ----------------
#define QT 4
#define CH 32
#define NCHUNK (CCN / CH)
#define ECPAD 132

__global__ __launch_bounds__(128)
void emission_softmax2(const float* __restrict__ Ec,
                       const float* __restrict__ Eq,
                       const int* __restrict__ mask,
                       const float* __restrict__ we_w,
                       const float* __restrict__ we_b,
                       float* __restrict__ attn)
{
    __shared__ float ecs[CH][ECPAD];
    __shared__ float eqs[QT][HH];
    __shared__ float wes[HH];
    __shared__ int ms[CH];

    const int b  = blockIdx.y;
    const int q0 = blockIdx.x * QT;
    const int tid = threadIdx.x;
    const int lane = tid & 31;
    const int q = tid >> 5;

    if (tid < HH) wes[tid] = we_w[tid];
    {
        const float4* src = (const float4*)&Eq[(long)(b * QQ + q0) * HH];
        float4* dst = (float4*)&eqs[0][0];
        for (int i = tid; i < QT * HH / 4; i += 128) dst[i] = src[i];
    }
    __syncthreads();

    float W = 0.f;
#pragma unroll
    for (int h = 0; h < HH; h += 4) {
        float4 w4 = *(const float4*)&wes[h];
        W += (w4.x + w4.y) + (w4.z + w4.w);
    }
    const float eb = we_b[0];

    float es_l[NCHUNK];

    for (int ch = 0; ch < NCHUNK; ch++) {
        __syncthreads();
        {
            const float4* src = (const float4*)&Ec[((long)b * CCN + ch * CH) * HH];
            for (int i = tid; i < CH * HH / 4; i += 128) {
                int r  = i >> 5;
                int c4 = (i & 31) * 4;
                *(float4*)&ecs[r][c4] = src[i];
            }
            if (tid < CH) ms[tid] = mask[b * CCN + ch * CH + tid];
        }
        __syncthreads();

        float s0 = 0.f, s1 = 0.f;
#pragma unroll
        for (int h = 0; h < HH; h += 8) {
            float4 e0 = *(const float4*)&ecs[lane][h];
            float4 g0 = *(const float4*)&eqs[q][h];
            float4 w0 = *(const float4*)&wes[h];
            float4 e1 = *(const float4*)&ecs[lane][h + 4];
            float4 g1 = *(const float4*)&eqs[q][h + 4];
            float4 w1 = *(const float4*)&wes[h + 4];
            s0 += w0.x * fast_rcp(fmaf(e0.x, g0.x, 1.f));
            s1 += w0.y * fast_rcp(fmaf(e0.y, g0.y, 1.f));
            s0 += w0.z * fast_rcp(fmaf(e0.z, g0.z, 1.f));
            s1 += w0.w * fast_rcp(fmaf(e0.w, g0.w, 1.f));
            s0 += w1.x * fast_rcp(fmaf(e1.x, g1.x, 1.f));
            s1 += w1.y * fast_rcp(fmaf(e1.y, g1.y, 1.f));
            s0 += w1.z * fast_rcp(fmaf(e1.z, g1.z, 1.f));
            s1 += w1.w * fast_rcp(fmaf(e1.w, g1.w, 1.f));
        }
        float s = s0 + s1;
        es_l[ch] = ms[lane] ? (fmaf(-2.f, s, W) + eb) : -INFINITY;
    }

    float lm = -INFINITY;
#pragma unroll
    for (int ch = 0; ch < NCHUNK; ch++) lm = fmaxf(lm, es_l[ch]);
#pragma unroll
    for (int off = 16; off >= 1; off >>= 1)
        lm = fmaxf(lm, __shfl_xor_sync(0xffffffffu, lm, off));
    const bool ok = (lm > -3.0e38f);

    float ls = 0.f;
#pragma unroll
    for (int ch = 0; ch < NCHUNK; ch++) {
        float e = ok ? __expf(es_l[ch] - lm) : 0.f;
        es_l[ch] = e;
        ls += e;
    }
#pragma unroll
    for (int off = 16; off >= 1; off >>= 1)
        ls += __shfl_xor_sync(0xffffffffu, ls, off);
    const float inv = (ls > 0.f) ? 1.f / ls : 0.f;

    float* arow = attn + (long)(b * QQ + q0 + q) * CCN;
#pragma unroll
    for (int ch = 0; ch < NCHUNK; ch++) arow[ch * CH + lane] = es_l[ch] * inv;
}

// ---------------- launcher ----------------
extern "C" void kernel_launch(void* const* d_in, const int* in_sizes, int n_in,
                              void* d_out, int out_size)
{
    const float* query   = (const float*)d_in[0];
    const float* context = (const float*)d_in[1];
    const int*   mask    = (const int*)d_in[2];
    const float* wq_w = (const float*)d_in[3];
    const float* wq_b = (const float*)d_in[4];
    const float* wc_w = (const float*)d_in[5];
    const float* wc_b = (const float*)d_in[6];
    const float* we_w = (const float*)d_in[7];
    const float* we_b = (const float*)d_in[8];
    const float* lo_w = (const float*)d_in[9];
    const float* lo_b = (const float*)d_in[10];

    float *Ec, *Eq, *qpart, *wc, *attn_s;
    cudaGetSymbolAddress((void**)&Ec, g_Ec);
    cudaGetSymbolAddress((void**)&Eq, g_Eq);
    cudaGetSymbolAddress((void**)&qpart, g_qpart);
    cudaGetSymbolAddress((void**)&wc, g_wc);
    cudaGetSymbolAddress((void**)&attn_s, g_attn_scratch);

    const int nOut  = BB * QQ * QDIM;
    const int nAttn = BB * QQ * CCN;
    float* outPtr  = nullptr;
    float* attnPtr = nullptr;
    if (out_size >= nOut + nAttn) {
        outPtr  = (float*)d_out;
        attnPtr = (float*)d_out + nOut;
    } else if (out_size == nAttn) {
        attnPtr = (float*)d_out;
    } else {
        outPtr = (float*)d_out;
    }
    if (!attnPtr) attnPtr = attn_s;

    // 1) all input-only projections in one launch: Ec, Eq, qpart (576 CTAs)
    proj_fused_kernel<<<576, 128>>>(context, query, wc_w, wc_b, wq_w, wq_b,
                                    lo_w, lo_b, Ec, Eq, qpart);

    // 2) emission + softmax -> attn (256 CTAs)
    emission_softmax2<<<dim3(QQ / QT, BB), 128>>>(Ec, Eq, mask, we_w, we_b, attnPtr);

    if (outPtr) {
        // 3) wc = attn @ context (256 CTAs)
        gemm_nn_kernel<<<dim3(CDIM / 64, QQ / 32, BB), 128>>>(attnPtr, context, wc);

        // 4) out = tanh(wc @ lo_w[:,:512].T + qpart) (256 CTAs)
        gemm_out_kernel<<<dim3(QDIM / 64, BB * QQ / 32), 128>>>(wc, lo_w, qpart, outPtr);
    }
}